// round 7
// baseline (speedup 1.0000x reference)
#include <cuda_runtime.h>
#include <math.h>

#define SPB       64
#define T_LEN     34
#define NTAB      340
#define BTHREADS  128           // 4 warps = 2 teams x 2 roles
#define JSTRIDE   35

__constant__ int c_flat[T_LEN] = {
    0,1,2,3,4,5,6,7,8,9, 11,
    0,1,2,3,4,5,6,7,8,9, 12,
    0,1,2,3,4,5,6,7,8,9, 10, 13
};

__device__ __forceinline__ float ex2f(float x) {
    float y;
    asm("ex2.approx.ftz.f32 %0, %1;" : "=f"(y) : "f"(x));
    return y;
}

// Contiguous queries q0..q0+NQ-1 in registers; single sweep over s.
template<int NQ>
__device__ __forceinline__ void attn_seg(int q0,
                                         const unsigned short* __restrict__ jrow,
                                         const char* __restrict__ tab,
                                         const char* __restrict__ mtab,
                                         float2* __restrict__ urow)
{
    float mx[NQ], my[NQ], mz[NQ], dn[NQ], bb[NQ];
    #pragma unroll
    for (int i = 0; i < NQ; ++i) {
        const float4 m = *(const float4*)(mtab + (int)jrow[q0 + i]);
        mx[i] = m.x; my[i] = m.y; mz[i] = m.z;
        dn[i] = 0.f; bb[i] = 0.f;
    }
    // all-active prefix: s = 0..q0
    #pragma unroll 2
    for (int s = 0; s <= q0; ++s) {
        const float4 kp = *(const float4*)(tab + (int)jrow[s]);
        #pragma unroll
        for (int i = 0; i < NQ; ++i) {
            float d = fmaf(mx[i], kp.x, fmaf(my[i], kp.y, mz[i] * kp.z));
            float e = ex2f(d);
            dn[i] += e;
            bb[i]  = fmaf(e, kp.w, bb[i]);
        }
    }
    urow[q0] = make_float2(dn[0], bb[0]);
    // expiry tail: one statically-unrolled step per remaining query
    #pragma unroll
    for (int seg = 1; seg < NQ; ++seg) {
        const float4 kp = *(const float4*)(tab + (int)jrow[q0 + seg]);
        #pragma unroll
        for (int i = seg; i < NQ; ++i) {
            float d = fmaf(mx[i], kp.x, fmaf(my[i], kp.y, mz[i] * kp.z));
            float e = ex2f(d);
            dn[i] += e;
            bb[i]  = fmaf(e, kp.w, bb[i]);
        }
        urow[q0 + seg] = make_float2(dn[seg], bb[seg]);
    }
}

__global__ __launch_bounds__(BTHREADS, 5)
void micro_fused7(
    const int*   __restrict__ idx,
    const float* __restrict__ tokA,
    const float* __restrict__ tokStart,
    const float* __restrict__ tokStride,
    const float* __restrict__ z_hi,
    const float* __restrict__ specialEq,
    const float* __restrict__ qW,         // (4,3)
    const float* __restrict__ phase,
    const float* __restrict__ outA,       // (5,)
    const float* __restrict__ outB,       // (5,)
    const float* __restrict__ nw,         // (5,)
    const float* __restrict__ fc1,        // (2,5)
    const float* __restrict__ hp,         // (2,5)
    float*       __restrict__ out,        // (B,34,10)
    int B)
{
    __shared__ float4 s_tab[NTAB];                  // (h2,h3,h4, v')
    __shared__ float4 s_m  [NTAB];                  // (m0,m1,m2, x4prenorm); 0.5*log2e baked
    __shared__ float4 s_x4 [NTAB];                  // pre-norm (x0,x1,p0,p1)
    __shared__ unsigned short s_j[SPB * JSTRIDE];   // byte offset (s*10+c)*16
    __shared__ float2 s_u  [SPB * T_LEN + 1];       // (den,b) -> in-place (u0,u1)
    __shared__ float  s_tt0[10], s_tt1[10];
    __shared__ float  s_cB[5], s_hp[10], s_wf[10], s_wh[10];

    const int  tid       = threadIdx.x;
    const long base_tok  = (long)blockIdx.x * (SPB * T_LEN);
    const long total_tok = (long)B * T_LEN;

    // ---- phase 1: coalesced idx load ----
    #pragma unroll
    for (int r = 0; r < 17; ++r) {
        int li = tid + r * BTHREADS;                // 0..2175
        int  yy = li / T_LEN;
        int  ss = li - yy * T_LEN;
        long g  = base_tok + li;
        int  v  = (g < total_tok) ? idx[g] : 0;
        s_j[yy * JSTRIDE + ss] = (unsigned short)((ss * 10 + v) << 4);
    }
    if (tid < 5)  s_cB[tid] = outB[tid];
    if (tid < 10) {
        s_hp[tid] = hp[tid];
        int cc = tid % 5;
        s_wf[tid] = nw[cc] * fc1[tid];
        s_wh[tid] = nw[cc] * hp[tid];
    }

    // ---- phase 2: build 340-entry tables ----
    #pragma unroll
    for (int r = 0; r < 3; ++r) {
        int i = tid + r * BTHREADS;
        if (i < NTAB) {
            const int tpos = i / 10;
            const int c    = i - tpos * 10;
            const int f    = c_flat[tpos];

            float p0, p1, p2;
            if (f < 10) {
                float a = 0.6283185307179586f * (float)f;
                p0 = 3.5f * __cosf(a);
                p1 = 3.5f * __sinf(a);
                p2 = 0.15f * (float)f;
            } else if (f == 10) {
                p0 = z_hi[0]; p1 = z_hi[1]; p2 = z_hi[2];
            } else if (f == 12) {
                p0 = specialEq[0]; p1 = specialEq[1]; p2 = specialEq[2];
            } else {
                p0 = p1 = p2 = 0.0f;
            }

            float ang = tokStart[0] + (float)c * tokStride[0];
            float amp = tokA[0];
            float x0 = amp * __cosf(ang);
            float x1 = amp * __sinf(ang);

            s_x4[i] = make_float4(x0, x1, p0, p1);
            if (tpos == 0) { s_tt0[c] = x0; s_tt1[c] = x1; }

            float ms = 0.2f * (x0*x0 + x1*x1 + p0*p0 + p1*p1 + p2*p2);
            float rr = rsqrtf(ms + 1e-5f);
            float h0 = x0 * rr * nw[0];
            float h1 = x1 * rr * nw[1];
            float h2 = p0 * rr * nw[2];
            float h3 = p1 * rr * nw[3];
            float h4 = p2 * rr * nw[4];

            float q0 = qW[0]*h2 + qW[1]*h3 + qW[2]*h4;
            float q1 = qW[3]*h2 + qW[4]*h3 + qW[5]*h4;
            float q2 = qW[6]*h2 + qW[7]*h3 + qW[8]*h4;
            float q3 = qW[9]*h2 + qW[10]*h3 + qW[11]*h4;

            float cp = __cosf(phase[0]);
            float sp = __sinf(phase[0]);
            float r0  = q0*cp - q1*sp;
            float r1v = q0*sp + q1*cp;
            float r2v = q2*cp - q3*sp;
            float r3  = q2*sp + q3*cp;
            const float LG = 0.5f * 1.4426950408889634f;
            float m0 = LG*(r0*qW[0] + r1v*qW[3] + r2v*qW[6] + r3*qW[9]);
            float m1 = LG*(r0*qW[1] + r1v*qW[4] + r2v*qW[7] + r3*qW[10]);
            float m2 = LG*(r0*qW[2] + r1v*qW[5] + r2v*qW[8] + r3*qW[11]);

            float w0s = hp[0]*outA[0] + hp[1]*outA[1] + hp[2]*outA[2] + hp[3]*outA[3] + hp[4]*outA[4];
            float w1s = hp[5]*outA[0] + hp[6]*outA[1] + hp[7]*outA[2] + hp[8]*outA[3] + hp[9]*outA[4];
            float vp  = h0*w0s + h1*w1s;

            s_tab[i] = make_float4(h2, h3, h4, vp);
            s_m[i]   = make_float4(m0, m1, m2, p2);
        }
    }
    __syncthreads();

    // ---- phase 3: attention. team = warp>>1 owns 32 seqs; 2 roles split queries
    //      role 0: {0..7} + {25..33}   (8 + 34 = 42 s-steps)
    //      role 1: {8..16} + {17..24}  (17 + 25 = 42 s-steps)
    {
        const int lane = tid & 31;
        const int warp = tid >> 5;
        const int team = warp >> 1;
        const int role = warp & 1;
        const int y    = lane + (team << 5);
        const unsigned short* __restrict__ jrow = s_j + y * JSTRIDE;
        const char* __restrict__ tab  = (const char*)s_tab;
        const char* __restrict__ mtab = (const char*)s_m;
        float2* __restrict__ urow = s_u + y * T_LEN;

        if (role == 0) {
            attn_seg<8>(0,  jrow, tab, mtab, urow);
            attn_seg<9>(25, jrow, tab, mtab, urow);
        } else {
            attn_seg<9>(8,  jrow, tab, mtab, urow);
            attn_seg<8>(17, jrow, tab, mtab, urow);
        }
    }
    __syncthreads();

    // ---- phase 4: uniform epilogue, in-place s_u: (den,b) -> (u0,u1) ----
    #pragma unroll
    for (int r = 0; r < 17; ++r) {
        int it = tid + r * BTHREADS;                // 0..2175
        const int y = it / T_LEN;
        const int t = it - y * T_LEN;
        const float2 db = s_u[it];
        const float dA = __fdividef(db.y, db.x);
        const int jt = (int)s_j[y * JSTRIDE + t];

        const float4 xv  = *(const float4*)((const char*)s_x4 + jt);
        const float  x4v = ((const float4*)((const char*)s_m + jt))->w;
        float X0 = fmaf(dA, s_cB[0], xv.x);
        float X1 = fmaf(dA, s_cB[1], xv.y);
        float X2 = fmaf(dA, s_cB[2], xv.z);
        float X3 = fmaf(dA, s_cB[3], xv.w);
        float X4 = fmaf(dA, s_cB[4], x4v);

        float ss1 = fmaf(X0,X0, fmaf(X1,X1, fmaf(X2,X2, fmaf(X3,X3, X4*X4))));
        float r1  = rsqrtf(fmaf(0.2f, ss1, 1e-5f));
        float z0 = r1 * (X0*s_wf[0] + X1*s_wf[1] + X2*s_wf[2] + X3*s_wf[3] + X4*s_wf[4]);
        float z1 = r1 * (X0*s_wf[5] + X1*s_wf[6] + X2*s_wf[7] + X3*s_wf[8] + X4*s_wf[9]);
        float g0 = 0.5f*z0*(1.0f + erff(z0 * 0.70710678118654752f));
        float g1 = 0.5f*z1*(1.0f + erff(z1 * 0.70710678118654752f));
        float Y0 = X0 + g0*s_hp[0] + g1*s_hp[5];
        float Y1 = X1 + g0*s_hp[1] + g1*s_hp[6];
        float Y2 = X2 + g0*s_hp[2] + g1*s_hp[7];
        float Y3 = X3 + g0*s_hp[3] + g1*s_hp[8];
        float Y4 = X4 + g0*s_hp[4] + g1*s_hp[9];

        float ss2 = fmaf(Y0,Y0, fmaf(Y1,Y1, fmaf(Y2,Y2, fmaf(Y3,Y3, Y4*Y4))));
        float r2  = rsqrtf(fmaf(0.2f, ss2, 1e-5f));
        float u0 = r2 * (Y0*s_wh[0] + Y1*s_wh[1] + Y2*s_wh[2] + Y3*s_wh[3] + Y4*s_wh[4]);
        float u1 = r2 * (Y0*s_wh[5] + Y1*s_wh[6] + Y2*s_wh[7] + Y3*s_wh[8] + Y4*s_wh[9]);

        s_u[it] = make_float2(u0, u1);
    }
    __syncthreads();

    // ---- phase 5: coalesced float4 output ----
    const long base_f  = base_tok * 10;
    const long total_f = total_tok * 10;
    float* __restrict__ ob = out + base_f;
    const int nf4 = (SPB * T_LEN * 10) / 4;         // 5440

    for (int f4 = tid; f4 < nf4; f4 += BTHREADS) {
        const int el = f4 * 4;
        if (base_f + el + 4 <= total_f) {
            int tq = el / 10;
            int d  = el - tq * 10;
            float2 u = s_u[tq];
            float vv[4];
            #pragma unroll
            for (int k2 = 0; k2 < 4; ++k2) {
                vv[k2] = fmaf(u.y, s_tt1[d], u.x * s_tt0[d]);
                if (++d == 10) { d = 0; ++tq; u = s_u[tq]; }
            }
            reinterpret_cast<float4*>(ob)[f4] = make_float4(vv[0], vv[1], vv[2], vv[3]);
        }
    }
}

extern "C" void kernel_launch(void* const* d_in, const int* in_sizes, int n_in,
                              void* d_out, int out_size)
{
    const int B = in_sizes[0] / T_LEN;
    const int grid = (B + SPB - 1) / SPB;
    micro_fused7<<<grid, BTHREADS>>>(
        (const int*)d_in[0],
        (const float*)d_in[1],
        (const float*)d_in[2],
        (const float*)d_in[3],
        (const float*)d_in[4],
        (const float*)d_in[5],
        (const float*)d_in[6],
        (const float*)d_in[7],
        (const float*)d_in[8],
        (const float*)d_in[9],
        (const float*)d_in[10],
        (const float*)d_in[11],
        (const float*)d_in[12],
        (float*)d_out, B);
}

// round 8
// speedup vs baseline: 1.6312x; 1.6312x over previous
#include <cuda_runtime.h>
#include <math.h>

#define SPB       64
#define T_LEN     34
#define NTAB      340
#define BTHREADS  256           // 8 warps = 2 teams x 4 roles
#define JSTRIDE   35

__constant__ int c_flat[T_LEN] = {
    0,1,2,3,4,5,6,7,8,9, 11,
    0,1,2,3,4,5,6,7,8,9, 12,
    0,1,2,3,4,5,6,7,8,9, 10, 13
};

__device__ __forceinline__ float ex2f(float x) {
    float y;
    asm("ex2.approx.ftz.f32 %0, %1;" : "=f"(y) : "f"(x));
    return y;
}
__device__ __forceinline__ float rcpf(float x) {
    float y;
    asm("rcp.approx.ftz.f32 %0, %1;" : "=f"(y) : "f"(x));
    return y;
}

// gelu(z) = 0.5 z (1 + erf(z/sqrt2)); erf via Abramowitz-Stegun 7.1.26 (|err|<=1.5e-7)
__device__ __forceinline__ float gelu_fast(float z) {
    float a  = z * 0.70710678118654752f;
    float ax = fabsf(a);
    float t  = rcpf(fmaf(0.3275911f, ax, 1.0f));
    float p  = t * fmaf(t, fmaf(t, fmaf(t, fmaf(t, 1.061405429f, -1.453152027f),
                                        1.421413741f), -0.284496736f), 0.254829592f);
    float em = ex2f(-1.4426950408889634f * a * a);
    float er = fmaf(-p, em, 1.0f);          // erf(|a|)
    er = copysignf(er, a);
    return 0.5f * z * (1.0f + er);
}

// Contiguous queries q0..q0+NQ-1 in registers; single sweep over s.
template<int NQ>
__device__ __forceinline__ void attn_seg(int q0,
                                         const unsigned short* __restrict__ jrow,
                                         const char* __restrict__ tab,
                                         const char* __restrict__ mtab,
                                         float2* __restrict__ urow)
{
    float mx[NQ], my[NQ], mz[NQ], dn[NQ], bb[NQ];
    #pragma unroll
    for (int i = 0; i < NQ; ++i) {
        const float4 m = *(const float4*)(mtab + (int)jrow[q0 + i]);
        mx[i] = m.x; my[i] = m.y; mz[i] = m.z;
        dn[i] = 0.f; bb[i] = 0.f;
    }
    #pragma unroll 2
    for (int s = 0; s <= q0; ++s) {
        const float4 kp = *(const float4*)(tab + (int)jrow[s]);
        #pragma unroll
        for (int i = 0; i < NQ; ++i) {
            float d = fmaf(mx[i], kp.x, fmaf(my[i], kp.y, mz[i] * kp.z));
            float e = ex2f(d);
            dn[i] += e;
            bb[i]  = fmaf(e, kp.w, bb[i]);
        }
    }
    urow[q0] = make_float2(dn[0], bb[0]);
    #pragma unroll
    for (int seg = 1; seg < NQ; ++seg) {
        const float4 kp = *(const float4*)(tab + (int)jrow[q0 + seg]);
        #pragma unroll
        for (int i = seg; i < NQ; ++i) {
            float d = fmaf(mx[i], kp.x, fmaf(my[i], kp.y, mz[i] * kp.z));
            float e = ex2f(d);
            dn[i] += e;
            bb[i]  = fmaf(e, kp.w, bb[i]);
        }
        urow[q0 + seg] = make_float2(dn[seg], bb[seg]);
    }
}

__global__ __launch_bounds__(BTHREADS, 5)
void micro_fused8(
    const int*   __restrict__ idx,
    const float* __restrict__ tokA,
    const float* __restrict__ tokStart,
    const float* __restrict__ tokStride,
    const float* __restrict__ z_hi,
    const float* __restrict__ specialEq,
    const float* __restrict__ qW,         // (4,3)
    const float* __restrict__ phase,
    const float* __restrict__ outA,       // (5,)
    const float* __restrict__ outB,       // (5,)
    const float* __restrict__ nw,         // (5,)
    const float* __restrict__ fc1,        // (2,5)
    const float* __restrict__ hp,         // (2,5)
    float*       __restrict__ out,        // (B,34,10)
    int B)
{
    __shared__ float4 s_tab[NTAB];
    __shared__ float4 s_m  [NTAB];
    __shared__ float4 s_x4 [NTAB];
    __shared__ unsigned short s_j[SPB * JSTRIDE];
    __shared__ float2 s_u  [SPB * T_LEN + 1];
    __shared__ float  s_tt0[10], s_tt1[10];
    __shared__ float  s_cB[5], s_hp[10], s_wf[10], s_wh[10];

    const int  tid       = threadIdx.x;
    const long base_tok  = (long)blockIdx.x * (SPB * T_LEN);
    const long total_tok = (long)B * T_LEN;

    // ---- phase 1: coalesced idx load ----
    #pragma unroll
    for (int r = 0; r < 9; ++r) {
        int li = tid + r * BTHREADS;                // 0..2303
        if (li < SPB * T_LEN) {
            int  yy = li / T_LEN;
            int  ss = li - yy * T_LEN;
            long g  = base_tok + li;
            int  v  = (g < total_tok) ? idx[g] : 0;
            s_j[yy * JSTRIDE + ss] = (unsigned short)((ss * 10 + v) << 4);
        }
    }
    if (tid < 5)  s_cB[tid] = outB[tid];
    if (tid < 10) {
        s_hp[tid] = hp[tid];
        int cc = tid % 5;
        s_wf[tid] = nw[cc] * fc1[tid];
        s_wh[tid] = nw[cc] * hp[tid];
    }

    // ---- phase 2: build 340-entry tables ----
    #pragma unroll
    for (int r = 0; r < 2; ++r) {
        int i = tid + r * BTHREADS;
        if (i < NTAB) {
            const int tpos = i / 10;
            const int c    = i - tpos * 10;
            const int f    = c_flat[tpos];

            float p0, p1, p2;
            if (f < 10) {
                float a = 0.6283185307179586f * (float)f;
                p0 = 3.5f * __cosf(a);
                p1 = 3.5f * __sinf(a);
                p2 = 0.15f * (float)f;
            } else if (f == 10) {
                p0 = z_hi[0]; p1 = z_hi[1]; p2 = z_hi[2];
            } else if (f == 12) {
                p0 = specialEq[0]; p1 = specialEq[1]; p2 = specialEq[2];
            } else {
                p0 = p1 = p2 = 0.0f;
            }

            float ang = tokStart[0] + (float)c * tokStride[0];
            float amp = tokA[0];
            float x0 = amp * __cosf(ang);
            float x1 = amp * __sinf(ang);

            s_x4[i] = make_float4(x0, x1, p0, p1);
            if (tpos == 0) { s_tt0[c] = x0; s_tt1[c] = x1; }

            float ms = 0.2f * (x0*x0 + x1*x1 + p0*p0 + p1*p1 + p2*p2);
            float rr = rsqrtf(ms + 1e-5f);
            float h0 = x0 * rr * nw[0];
            float h1 = x1 * rr * nw[1];
            float h2 = p0 * rr * nw[2];
            float h3 = p1 * rr * nw[3];
            float h4 = p2 * rr * nw[4];

            float q0 = qW[0]*h2 + qW[1]*h3 + qW[2]*h4;
            float q1 = qW[3]*h2 + qW[4]*h3 + qW[5]*h4;
            float q2 = qW[6]*h2 + qW[7]*h3 + qW[8]*h4;
            float q3 = qW[9]*h2 + qW[10]*h3 + qW[11]*h4;

            float cp = __cosf(phase[0]);
            float sp = __sinf(phase[0]);
            float r0  = q0*cp - q1*sp;
            float r1v = q0*sp + q1*cp;
            float r2v = q2*cp - q3*sp;
            float r3  = q2*sp + q3*cp;
            const float LG = 0.5f * 1.4426950408889634f;
            float m0 = LG*(r0*qW[0] + r1v*qW[3] + r2v*qW[6] + r3*qW[9]);
            float m1 = LG*(r0*qW[1] + r1v*qW[4] + r2v*qW[7] + r3*qW[10]);
            float m2 = LG*(r0*qW[2] + r1v*qW[5] + r2v*qW[8] + r3*qW[11]);

            float w0s = hp[0]*outA[0] + hp[1]*outA[1] + hp[2]*outA[2] + hp[3]*outA[3] + hp[4]*outA[4];
            float w1s = hp[5]*outA[0] + hp[6]*outA[1] + hp[7]*outA[2] + hp[8]*outA[3] + hp[9]*outA[4];
            float vp  = h0*w0s + h1*w1s;

            s_tab[i] = make_float4(h2, h3, h4, vp);
            s_m[i]   = make_float4(m0, m1, m2, p2);
        }
    }
    __syncthreads();

    // ---- phase 3: attention. 8 warps = 2 teams x 4 roles; NQ<=5, balanced 39-40 s-steps
    {
        const int lane = tid & 31;
        const int warp = tid >> 5;
        const int team = warp >> 2;
        const int role = warp & 3;
        const int y    = lane + (team << 5);
        const unsigned short* __restrict__ jrow = s_j + y * JSTRIDE;
        const char* __restrict__ tab  = (const char*)s_tab;
        const char* __restrict__ mtab = (const char*)s_m;
        float2* __restrict__ urow = s_u + y * T_LEN;

        if (role == 0) {
            attn_seg<4>(30, jrow, tab, mtab, urow);   // 34 steps
            attn_seg<5>(0,  jrow, tab, mtab, urow);   // 5
        } else if (role == 1) {
            attn_seg<4>(26, jrow, tab, mtab, urow);   // 30
            attn_seg<5>(5,  jrow, tab, mtab, urow);   // 10
        } else if (role == 2) {
            attn_seg<4>(22, jrow, tab, mtab, urow);   // 26
            attn_seg<4>(10, jrow, tab, mtab, urow);   // 14
        } else {
            attn_seg<4>(18, jrow, tab, mtab, urow);   // 22
            attn_seg<4>(14, jrow, tab, mtab, urow);   // 18
        }
    }
    __syncthreads();

    // ---- phase 4: uniform epilogue, in-place s_u: (den,b) -> (u0,u1) ----
    #pragma unroll
    for (int r = 0; r < 9; ++r) {
        int it = tid + r * BTHREADS;
        if (it < SPB * T_LEN) {
            const int y = it / T_LEN;
            const int t = it - y * T_LEN;
            const float2 db = s_u[it];
            const float dA = __fdividef(db.y, db.x);
            const int jt = (int)s_j[y * JSTRIDE + t];

            const float4 xv  = *(const float4*)((const char*)s_x4 + jt);
            const float  x4v = ((const float4*)((const char*)s_m + jt))->w;
            float X0 = fmaf(dA, s_cB[0], xv.x);
            float X1 = fmaf(dA, s_cB[1], xv.y);
            float X2 = fmaf(dA, s_cB[2], xv.z);
            float X3 = fmaf(dA, s_cB[3], xv.w);
            float X4 = fmaf(dA, s_cB[4], x4v);

            float ss1 = fmaf(X0,X0, fmaf(X1,X1, fmaf(X2,X2, fmaf(X3,X3, X4*X4))));
            float r1  = rsqrtf(fmaf(0.2f, ss1, 1e-5f));
            float z0 = r1 * (X0*s_wf[0] + X1*s_wf[1] + X2*s_wf[2] + X3*s_wf[3] + X4*s_wf[4]);
            float z1 = r1 * (X0*s_wf[5] + X1*s_wf[6] + X2*s_wf[7] + X3*s_wf[8] + X4*s_wf[9]);
            float g0 = gelu_fast(z0);
            float g1 = gelu_fast(z1);
            float Y0 = X0 + g0*s_hp[0] + g1*s_hp[5];
            float Y1 = X1 + g0*s_hp[1] + g1*s_hp[6];
            float Y2 = X2 + g0*s_hp[2] + g1*s_hp[7];
            float Y3 = X3 + g0*s_hp[3] + g1*s_hp[8];
            float Y4 = X4 + g0*s_hp[4] + g1*s_hp[9];

            float ss2 = fmaf(Y0,Y0, fmaf(Y1,Y1, fmaf(Y2,Y2, fmaf(Y3,Y3, Y4*Y4))));
            float r2  = rsqrtf(fmaf(0.2f, ss2, 1e-5f));
            float u0 = r2 * (Y0*s_wh[0] + Y1*s_wh[1] + Y2*s_wh[2] + Y3*s_wh[3] + Y4*s_wh[4]);
            float u1 = r2 * (Y0*s_wh[5] + Y1*s_wh[6] + Y2*s_wh[7] + Y3*s_wh[8] + Y4*s_wh[9]);

            s_u[it] = make_float2(u0, u1);
        }
    }
    __syncthreads();

    // ---- phase 5: coalesced float4 output ----
    const long base_f  = base_tok * 10;
    const long total_f = total_tok * 10;
    float* __restrict__ ob = out + base_f;
    const int nf4 = (SPB * T_LEN * 10) / 4;         // 5440

    for (int f4 = tid; f4 < nf4; f4 += BTHREADS) {
        const int el = f4 * 4;
        if (base_f + el + 4 <= total_f) {
            int tq = el / 10;
            int d  = el - tq * 10;
            float2 u = s_u[tq];
            float vv[4];
            #pragma unroll
            for (int k2 = 0; k2 < 4; ++k2) {
                vv[k2] = fmaf(u.y, s_tt1[d], u.x * s_tt0[d]);
                if (++d == 10) { d = 0; ++tq; u = s_u[tq]; }
            }
            reinterpret_cast<float4*>(ob)[f4] = make_float4(vv[0], vv[1], vv[2], vv[3]);
        }
    }
}

extern "C" void kernel_launch(void* const* d_in, const int* in_sizes, int n_in,
                              void* d_out, int out_size)
{
    const int B = in_sizes[0] / T_LEN;
    const int grid = (B + SPB - 1) / SPB;
    micro_fused8<<<grid, BTHREADS>>>(
        (const int*)d_in[0],
        (const float*)d_in[1],
        (const float*)d_in[2],
        (const float*)d_in[3],
        (const float*)d_in[4],
        (const float*)d_in[5],
        (const float*)d_in[6],
        (const float*)d_in[7],
        (const float*)d_in[8],
        (const float*)d_in[9],
        (const float*)d_in[10],
        (const float*)d_in[11],
        (const float*)d_in[12],
        (float*)d_out, B);
}